// round 11
// baseline (speedup 1.0000x reference)
#include <cuda_runtime.h>

// out[i] = -(x0*x0 - x0 + x1*x1 - x1) = x0*(1-x0) + x1*(1-x1), A = 1.0
// N = 16777216 rows; input [N,2] fp32, output [N,1] fp32. HBM-streaming bound,
// operating at ~75-78% of 8TB/s spec (mixed 2:1 read:write stream ceiling).
//
// Shape fixed at R2 best (2x float4 loads, 1x float4 store per thread,
// 16384x256). R9 keeps __stcs store (best harness: 32.9us). This round's
// single variable: __ldcg loads (skip L1 — zero-reuse stream, L1 fills are
// pure overhead; unlike R5, load COUNT per thread is unchanged).

__global__ void __launch_bounds__(256) poi2d_kernel(const float4* __restrict__ in,
                                                    float4* __restrict__ out,
                                                    int n_quads) {
    int i = blockIdx.x * blockDim.x + threadIdx.x;
    if (i < n_quads) {
        float4 a = __ldcg(&in[2 * i]);
        float4 b = __ldcg(&in[2 * i + 1]);
        float4 r;
        r.x = fmaf(a.x, 1.0f - a.x, a.y * (1.0f - a.y));
        r.y = fmaf(a.z, 1.0f - a.z, a.w * (1.0f - a.w));
        r.z = fmaf(b.x, 1.0f - b.x, b.y * (1.0f - b.y));
        r.w = fmaf(b.z, 1.0f - b.z, b.w * (1.0f - b.w));
        __stcs(&out[i], r);
    }
}

extern "C" void kernel_launch(void* const* d_in, const int* in_sizes, int n_in,
                              void* d_out, int out_size) {
    const float* in = (const float*)d_in[0];
    float* out = (float*)d_out;
    int n_rows = out_size;        // 16777216
    int n_quads = n_rows / 4;     // 4 rows (one float4 of outputs) per thread

    int threads = 256;
    int blocks = (n_quads + threads - 1) / threads;  // 16384
    poi2d_kernel<<<blocks, threads>>>((const float4*)in, (float4*)out, n_quads);
}